// round 2
// baseline (speedup 1.0000x reference)
#include <cuda_runtime.h>

// ---------------------------------------------------------------------------
// LocalAttentionND: x(2,64,64,256) -> qkv GEMM -> rmsnorm+rope -> 7x7 local
// soft-masked attention -> rmsnorm -> gate merge -> out GEMM.
// Round 1: fp32 SIMT baseline, fused epilogues, L2-resident attention gathers.
// ---------------------------------------------------------------------------

static constexpr int NTOK = 8192;      // 2*64*64
static constexpr int CDIM = 256;
static constexpr int QKVN = 768;

// scratch (static device allocations are allowed)
__device__ float g_qkv[NTOK * QKVN];     // silu(x@W_qkv); q/k rewritten in-place
__device__ float g_wp[NTOK * 8];         // width[4], sharp[4] per token (post-transform)
__device__ float g_outn[NTOK * CDIM];    // rmsnorm(attention out)
__device__ float g_merged[NTOK * CDIM];  // gate*v + (1-gate)*outn

__device__ __forceinline__ float fsig(float x)  { return 1.f / (1.f + __expf(-x)); }
__device__ __forceinline__ float fsilu(float x) { return x   / (1.f + __expf(-x)); }

// ---------------------------------------------------------------------------
// GEMM: Cout = epi(A[M,256] @ W[256,N] (+bias)).  Tiles 64x64x16, 256 thr,
// 4x4 microtile. EPI=0: silu. EPI=1: gate-merge (A is v, outn blended in).
// ---------------------------------------------------------------------------
template <int EPI>
__global__ void __launch_bounds__(256) gemm_k256(
    const float* __restrict__ A, int lda,
    const float* __restrict__ W, int ldw,
    const float* __restrict__ bias,
    float* __restrict__ Cout, int ldc,
    const float* __restrict__ outn)
{
    __shared__ __align__(16) float As[16][65];   // [k][m], padded: conflict-free
    __shared__ __align__(16) float Bs[16][64];   // [k][n]

    const int tid = threadIdx.x;
    const int tx = tid & 15, ty = tid >> 4;
    const int row0 = blockIdx.x * 64;
    const int col0 = blockIdx.y * 64;

    const int arow = tid >> 2;            // 0..63
    const int acol = (tid & 3) << 2;      // 0,4,8,12
    const int brow = tid >> 4;            // 0..15
    const int bcol = (tid & 15) << 2;     // 0..60

    const float* Ap = A + (size_t)(row0 + arow) * lda + acol;
    const float* Wp = W + (size_t)brow * ldw + col0 + bcol;

    float acc[4][4] = {};

    for (int k0 = 0; k0 < 256; k0 += 16) {
        float4 a4 = *(const float4*)(Ap + k0);
        As[acol + 0][arow] = a4.x;
        As[acol + 1][arow] = a4.y;
        As[acol + 2][arow] = a4.z;
        As[acol + 3][arow] = a4.w;
        float4 b4 = *(const float4*)(Wp + (size_t)k0 * ldw);
        *(float4*)&Bs[brow][bcol] = b4;
        __syncthreads();
#pragma unroll
        for (int kk = 0; kk < 16; kk++) {
            float a0 = As[kk][ty * 4 + 0];
            float a1 = As[kk][ty * 4 + 1];
            float a2 = As[kk][ty * 4 + 2];
            float a3 = As[kk][ty * 4 + 3];
            float4 b = *(const float4*)&Bs[kk][tx * 4];
            acc[0][0] += a0 * b.x; acc[0][1] += a0 * b.y; acc[0][2] += a0 * b.z; acc[0][3] += a0 * b.w;
            acc[1][0] += a1 * b.x; acc[1][1] += a1 * b.y; acc[1][2] += a1 * b.z; acc[1][3] += a1 * b.w;
            acc[2][0] += a2 * b.x; acc[2][1] += a2 * b.y; acc[2][2] += a2 * b.z; acc[2][3] += a2 * b.w;
            acc[3][0] += a3 * b.x; acc[3][1] += a3 * b.y; acc[3][2] += a3 * b.z; acc[3][3] += a3 * b.w;
        }
        __syncthreads();
    }

#pragma unroll
    for (int i = 0; i < 4; i++) {
        int row = row0 + ty * 4 + i;
        int col = col0 + tx * 4;
        float4 r;
        if (EPI == 0) {
            r.x = fsilu(acc[i][0]);
            r.y = fsilu(acc[i][1]);
            r.z = fsilu(acc[i][2]);
            r.w = fsilu(acc[i][3]);
        } else {
            float4 v4 = *(const float4*)(A + (size_t)row * lda + col);
            float4 o4 = *(const float4*)(outn + (size_t)row * CDIM + col);
            float4 b4 = *(const float4*)(bias + col);
            float g;
            g = fsig(fsilu(acc[i][0] + b4.x)); r.x = g * v4.x + (1.f - g) * o4.x;
            g = fsig(fsilu(acc[i][1] + b4.y)); r.y = g * v4.y + (1.f - g) * o4.y;
            g = fsig(fsilu(acc[i][2] + b4.z)); r.z = g * v4.z + (1.f - g) * o4.z;
            g = fsig(fsilu(acc[i][3] + b4.w)); r.w = g * v4.w + (1.f - g) * o4.w;
        }
        *(float4*)(Cout + (size_t)row * ldc + col) = r;
    }
}

// ---------------------------------------------------------------------------
// wp = silu(x @ W_wp + b_wp); width = sig(wp[:4])*maxd+0.5, sharp = sig(wp[4:])*9.5+0.5
// one warp per token
// ---------------------------------------------------------------------------
__global__ void __launch_bounds__(256) wp_kernel(
    const float* __restrict__ x, const float* __restrict__ W_wp,
    const float* __restrict__ b_wp, float* __restrict__ wp_out)
{
    int warp = (blockIdx.x * blockDim.x + threadIdx.x) >> 5;
    int lane = threadIdx.x & 31;
    if (warp >= NTOK) return;
    const float* xr = x + (size_t)warp * CDIM;
    float acc[8] = {};
    for (int k = lane; k < CDIM; k += 32) {
        float xv = xr[k];
        const float* wr = W_wp + k * 8;
#pragma unroll
        for (int o = 0; o < 8; o++) acc[o] += xv * wr[o];
    }
#pragma unroll
    for (int o = 0; o < 8; o++)
#pragma unroll
        for (int off = 16; off; off >>= 1)
            acc[o] += __shfl_xor_sync(0xffffffffu, acc[o], off);
    if (lane < 8) {
        const float maxd = 4.242640687119285f;  // sqrt(18)
        float t = acc[lane] + b_wp[lane];
        float s = fsilu(t);
        float sg = fsig(s);
        wp_out[warp * 8 + lane] = (lane < 4) ? (sg * maxd + 0.5f) : (sg * 9.5f + 0.5f);
    }
}

// ---------------------------------------------------------------------------
// In-place rmsnorm (per head, D=64) + RoPE (position = head index) on q and k.
// 8 warps/block: warp = which(q/k)*4 + head; one block per token.
// ---------------------------------------------------------------------------
__global__ void __launch_bounds__(256) rmsrope_kernel(
    const float* __restrict__ w_qnorm, const float* __restrict__ w_knorm)
{
    int token = blockIdx.x;
    int warpId = threadIdx.x >> 5, lane = threadIdx.x & 31;
    int which = warpId >> 2;    // 0=q, 1=k
    int head  = warpId & 3;
    const float* wn = which ? w_knorm : w_qnorm;
    float* base = g_qkv + (size_t)token * QKVN + which * CDIM + head * 64;

    float x1 = base[lane], x2 = base[lane + 32];
    float ss = x1 * x1 + x2 * x2;
#pragma unroll
    for (int off = 16; off; off >>= 1) ss += __shfl_xor_sync(0xffffffffu, ss, off);
    float inv = rsqrtf(ss * (1.f / 64.f) + 1e-6f);
    x1 = x1 * inv * wn[lane];
    x2 = x2 * inv * wn[lane + 32];

    // freqs[j] = 10000^{-j/32}; ang = head * freqs[lane]
    float freq = exp2f(-(float)lane * (13.287712379549449f / 32.f));
    float ang = (float)head * freq;
    float c = cosf(ang), s = sinf(ang);
    base[lane]      = x1 * c - x2 * s;
    base[lane + 32] = x1 * s + x2 * c;
}

// ---------------------------------------------------------------------------
// Attention: 1 warp per (token, head), 2 tokens per 256-thread block.
// 49-window scores + soft distance mask + softmax + weighted-v,
// fused per-token rmsnorm (cross-head via smem) -> g_outn.
// OOB windows mimic zero-padded k/v: score contribution 0, v contribution 0,
// but still participate in the softmax (mask penalty applied).
// ---------------------------------------------------------------------------
__global__ void __launch_bounds__(256) attn_kernel(const float* __restrict__ w_onorm)
{
    __shared__ float s_out[2][256];
    __shared__ float s_ss[2];

    int warpId = threadIdx.x >> 5, lane = threadIdx.x & 31;
    int tl = warpId >> 2;      // token-local 0/1
    int head = warpId & 3;
    int token = blockIdx.x * 2 + tl;
    int b = token >> 12;
    int yx = token & 4095;
    int y = yx >> 6, xx = yx & 63;

    if (threadIdx.x < 2) s_ss[threadIdx.x] = 0.f;

    const float* qrow = g_qkv + (size_t)token * QKVN + head * 64;
    float q0 = qrow[lane], q1 = qrow[lane + 32];
    float width = g_wp[token * 8 + head];
    float sharp = g_wp[token * 8 + 4 + head];

    float sc[49];
#pragma unroll
    for (int w = 0; w < 49; w++) {
        int di = w / 7 - 3, dj = w % 7 - 3;
        int ny = y + di, nx = xx + dj;
        bool inb = ((unsigned)ny < 64u) & ((unsigned)nx < 64u);
        float dot = 0.f;
        if (inb) {
            int ntok = (b << 12) + (ny << 6) + nx;
            const float* krow = g_qkv + (size_t)ntok * QKVN + 256 + head * 64;
            dot = q0 * krow[lane] + q1 * krow[lane + 32];
        }
#pragma unroll
        for (int off = 16; off; off >>= 1) dot += __shfl_xor_sync(0xffffffffu, dot, off);
        float rd = sqrtf((float)(di * di + dj * dj));
        float mask = fsig((width - rd) * sharp);
        sc[w] = dot * 0.125f - (1.f - mask) * 10000.f;
    }

    float mx = -1e30f;
#pragma unroll
    for (int w = 0; w < 49; w++) mx = fmaxf(mx, sc[w]);
    float denom = 0.f;
#pragma unroll
    for (int w = 0; w < 49; w++) { sc[w] = __expf(sc[w] - mx); denom += sc[w]; }

    float o0 = 0.f, o1 = 0.f;
#pragma unroll
    for (int w = 0; w < 49; w++) {
        int di = w / 7 - 3, dj = w % 7 - 3;
        int ny = y + di, nx = xx + dj;
        if (((unsigned)ny < 64u) & ((unsigned)nx < 64u)) {
            int ntok = (b << 12) + (ny << 6) + nx;
            const float* vrow = g_qkv + (size_t)ntok * QKVN + 512 + head * 64;
            o0 += sc[w] * vrow[lane];
            o1 += sc[w] * vrow[lane + 32];
        }
    }
    float rdm = 1.f / denom;
    o0 *= rdm; o1 *= rdm;

    s_out[tl][head * 64 + lane]      = o0;
    s_out[tl][head * 64 + lane + 32] = o1;

    float pss = o0 * o0 + o1 * o1;
#pragma unroll
    for (int off = 16; off; off >>= 1) pss += __shfl_xor_sync(0xffffffffu, pss, off);
    __syncthreads();            // s_ss init + s_out visible
    if (lane == 0) atomicAdd(&s_ss[tl], pss);
    __syncthreads();

    for (int e = threadIdx.x; e < 512; e += 256) {
        int t2 = e >> 8, c = e & 255;
        float rinv = rsqrtf(s_ss[t2] * (1.f / 256.f) + 1e-6f);
        g_outn[(size_t)(blockIdx.x * 2 + t2) * CDIM + c] = s_out[t2][c] * rinv * w_onorm[c];
    }
}

// ---------------------------------------------------------------------------
extern "C" void kernel_launch(void* const* d_in, const int* in_sizes, int n_in,
                              void* d_out, int out_size)
{
    const float* x       = (const float*)d_in[0];
    const float* W_qkv   = (const float*)d_in[1];
    const float* w_qnorm = (const float*)d_in[2];
    const float* w_knorm = (const float*)d_in[3];
    const float* W_wp    = (const float*)d_in[4];
    const float* b_wp    = (const float*)d_in[5];
    const float* w_onorm = (const float*)d_in[6];
    const float* W_out   = (const float*)d_in[7];
    const float* W_gate  = (const float*)d_in[8];
    const float* b_gate  = (const float*)d_in[9];
    float* out = (float*)d_out;

    float *p_qkv, *p_wp, *p_outn, *p_merged;
    cudaGetSymbolAddress((void**)&p_qkv, g_qkv);
    cudaGetSymbolAddress((void**)&p_wp, g_wp);
    cudaGetSymbolAddress((void**)&p_outn, g_outn);
    cudaGetSymbolAddress((void**)&p_merged, g_merged);

    // 1. qkv = silu(x @ W_qkv)
    gemm_k256<0><<<dim3(NTOK / 64, QKVN / 64), 256>>>(x, CDIM, W_qkv, QKVN, nullptr,
                                                      p_qkv, QKVN, nullptr);
    // 2. width/sharpness projection
    wp_kernel<<<NTOK / 8, 256>>>(x, W_wp, b_wp, p_wp);
    // 3. rmsnorm + rope on q, k (in place)
    rmsrope_kernel<<<NTOK, 256>>>(w_qnorm, w_knorm);
    // 4. windowed attention + fused output rmsnorm
    attn_kernel<<<NTOK / 2, 256>>>(w_onorm);
    // 5. gate GEMM + merge epilogue: merged = gate*v + (1-gate)*outn
    gemm_k256<1><<<dim3(NTOK / 64, CDIM / 64), 256>>>(p_qkv + 512, QKVN, W_gate, CDIM,
                                                      b_gate, p_merged, CDIM, p_outn);
    // 6. final: silu(merged @ W_out)
    gemm_k256<0><<<dim3(NTOK / 64, CDIM / 64), 256>>>(p_merged, CDIM, W_out, CDIM, nullptr,
                                                      out, CDIM, nullptr);
}

// round 3
// speedup vs baseline: 1.6526x; 1.6526x over previous
#include <cuda_runtime.h>

// ---------------------------------------------------------------------------
// LocalAttentionND: x(2,64,64,256) -> qkv GEMM -> rmsnorm+rope -> 7x7 local
// soft-masked attention -> rmsnorm -> gate merge -> out GEMM.
// Round 2: attention restructured (lane=window score phase, no per-dot
// shuffles, coalesced v phase, low regs); GEMM 128x64 tile, 8x4 microtile.
// ---------------------------------------------------------------------------

static constexpr int NTOK = 8192;      // 2*64*64
static constexpr int CDIM = 256;
static constexpr int QKVN = 768;

__device__ float g_qkv[NTOK * QKVN];     // silu(x@W_qkv); q/k rewritten in-place
__device__ float g_wp[NTOK * 8];         // width[4], sharp[4] per token
__device__ float g_outn[NTOK * CDIM];    // rmsnorm(attention out)
__device__ float g_merged[NTOK * CDIM];  // gate*v + (1-gate)*outn

__device__ __forceinline__ float fsig(float x)  { return 1.f / (1.f + __expf(-x)); }
__device__ __forceinline__ float fsilu(float x) { return x   / (1.f + __expf(-x)); }

// ---------------------------------------------------------------------------
// GEMM: Cout = epi(A[M,256] @ W[256,N] (+bias)). Tile 128x64x16, 256 thr,
// 8x4 microtile. EPI=0: silu. EPI=1: gate-merge (A is v, outn blended in).
// ---------------------------------------------------------------------------
template <int EPI>
__global__ void __launch_bounds__(256) gemm_k256(
    const float* __restrict__ A, int lda,
    const float* __restrict__ W, int ldw,
    const float* __restrict__ bias,
    float* __restrict__ Cout, int ldc,
    const float* __restrict__ outn)
{
    __shared__ __align__(16) float As[16][132];  // [k][m], stride 132: 16B-aligned rows
    __shared__ __align__(16) float Bs[16][64];   // [k][n]

    const int tid = threadIdx.x;
    const int tx = tid & 15;       // col group (x4)
    const int ty = tid >> 4;       // 0..15 -> rows ty*8..ty*8+7
    const int row0 = blockIdx.x * 128;
    const int col0 = blockIdx.y * 64;

    const int arow = tid >> 1;           // 0..127
    const int acol = (tid & 1) * 8;      // 0 or 8
    const int brow = tid >> 4;           // 0..15
    const int bcol = (tid & 15) * 4;     // 0..60

    const float* Ap = A + (size_t)(row0 + arow) * lda + acol;
    const float* Wp = W + (size_t)brow * ldw + col0 + bcol;

    float acc[8][4] = {};

    for (int k0 = 0; k0 < 256; k0 += 16) {
        float4 a0 = *(const float4*)(Ap + k0);
        float4 a1 = *(const float4*)(Ap + k0 + 4);
        As[acol + 0][arow] = a0.x; As[acol + 1][arow] = a0.y;
        As[acol + 2][arow] = a0.z; As[acol + 3][arow] = a0.w;
        As[acol + 4][arow] = a1.x; As[acol + 5][arow] = a1.y;
        As[acol + 6][arow] = a1.z; As[acol + 7][arow] = a1.w;
        *(float4*)&Bs[brow][bcol] = *(const float4*)(Wp + (size_t)k0 * ldw);
        __syncthreads();
#pragma unroll
        for (int kk = 0; kk < 16; kk++) {
            float4 b  = *(const float4*)&Bs[kk][tx * 4];
            float4 x0 = *(const float4*)&As[kk][ty * 8];
            float4 x1 = *(const float4*)&As[kk][ty * 8 + 4];
            float av[8] = {x0.x, x0.y, x0.z, x0.w, x1.x, x1.y, x1.z, x1.w};
#pragma unroll
            for (int i = 0; i < 8; i++) {
                acc[i][0] += av[i] * b.x;
                acc[i][1] += av[i] * b.y;
                acc[i][2] += av[i] * b.z;
                acc[i][3] += av[i] * b.w;
            }
        }
        __syncthreads();
    }

#pragma unroll
    for (int i = 0; i < 8; i++) {
        int row = row0 + ty * 8 + i;
        int col = col0 + tx * 4;
        float4 r;
        if (EPI == 0) {
            r.x = fsilu(acc[i][0]);
            r.y = fsilu(acc[i][1]);
            r.z = fsilu(acc[i][2]);
            r.w = fsilu(acc[i][3]);
        } else {
            float4 v4 = *(const float4*)(A + (size_t)row * lda + col);
            float4 o4 = *(const float4*)(outn + (size_t)row * CDIM + col);
            float4 b4 = *(const float4*)(bias + col);
            float g;
            g = fsig(fsilu(acc[i][0] + b4.x)); r.x = g * v4.x + (1.f - g) * o4.x;
            g = fsig(fsilu(acc[i][1] + b4.y)); r.y = g * v4.y + (1.f - g) * o4.y;
            g = fsig(fsilu(acc[i][2] + b4.z)); r.z = g * v4.z + (1.f - g) * o4.z;
            g = fsig(fsilu(acc[i][3] + b4.w)); r.w = g * v4.w + (1.f - g) * o4.w;
        }
        *(float4*)(Cout + (size_t)row * ldc + col) = r;
    }
}

// ---------------------------------------------------------------------------
// wp = silu(x @ W_wp + b_wp); width = sig(.)*maxd+0.5, sharp = sig(.)*9.5+0.5
// one warp per token
// ---------------------------------------------------------------------------
__global__ void __launch_bounds__(256) wp_kernel(
    const float* __restrict__ x, const float* __restrict__ W_wp,
    const float* __restrict__ b_wp, float* __restrict__ wp_out)
{
    int warp = (blockIdx.x * blockDim.x + threadIdx.x) >> 5;
    int lane = threadIdx.x & 31;
    if (warp >= NTOK) return;
    const float* xr = x + (size_t)warp * CDIM;
    float acc[8] = {};
    for (int k = lane; k < CDIM; k += 32) {
        float xv = xr[k];
        const float* wr = W_wp + k * 8;
#pragma unroll
        for (int o = 0; o < 8; o++) acc[o] += xv * wr[o];
    }
#pragma unroll
    for (int o = 0; o < 8; o++)
#pragma unroll
        for (int off = 16; off; off >>= 1)
            acc[o] += __shfl_xor_sync(0xffffffffu, acc[o], off);
    if (lane < 8) {
        const float maxd = 4.242640687119285f;  // sqrt(18)
        float t = acc[lane] + b_wp[lane];
        float s = fsilu(t);
        float sg = fsig(s);
        wp_out[warp * 8 + lane] = (lane < 4) ? (sg * maxd + 0.5f) : (sg * 9.5f + 0.5f);
    }
}

// ---------------------------------------------------------------------------
// In-place rmsnorm (per head, D=64) + RoPE (position = head index) on q, k.
// ---------------------------------------------------------------------------
__global__ void __launch_bounds__(256) rmsrope_kernel(
    const float* __restrict__ w_qnorm, const float* __restrict__ w_knorm)
{
    int token = blockIdx.x;
    int warpId = threadIdx.x >> 5, lane = threadIdx.x & 31;
    int which = warpId >> 2;    // 0=q, 1=k
    int head  = warpId & 3;
    const float* wn = which ? w_knorm : w_qnorm;
    float* base = g_qkv + (size_t)token * QKVN + which * CDIM + head * 64;

    float x1 = base[lane], x2 = base[lane + 32];
    float ss = x1 * x1 + x2 * x2;
#pragma unroll
    for (int off = 16; off; off >>= 1) ss += __shfl_xor_sync(0xffffffffu, ss, off);
    float inv = rsqrtf(ss * (1.f / 64.f) + 1e-6f);
    x1 = x1 * inv * wn[lane];
    x2 = x2 * inv * wn[lane + 32];

    float freq = exp2f(-(float)lane * (13.287712379549449f / 32.f));  // log2(10000)/32
    float ang = (float)head * freq;
    float c = cosf(ang), s = sinf(ang);
    base[lane]      = x1 * c - x2 * s;
    base[lane + 32] = x1 * s + x2 * c;
}

// ---------------------------------------------------------------------------
// Attention: 1 warp per (token, head), 2 tokens per 256-thread block.
// Phase 1: lane = window (2 rounds over 49): full 64-dot per lane, no shuffles.
// Phase 2: warp-softmax over lane-held scores, probs -> smem.
// Phase 3: lane = channel, coalesced v gathers. Fused per-token rmsnorm.
// OOB windows: dot=0 / v=0 (ref zero-padding) but mask penalty still applies.
// ---------------------------------------------------------------------------
__global__ void __launch_bounds__(256) attn_kernel(const float* __restrict__ w_onorm)
{
    __shared__ __align__(16) float s_q[8][64];
    __shared__ float s_p[8][52];
    __shared__ float s_out[2][256];
    __shared__ float s_ss[2];

    const int warpId = threadIdx.x >> 5, lane = threadIdx.x & 31;
    const int tl = warpId >> 2;      // token-local 0/1
    const int head = warpId & 3;
    const int token = blockIdx.x * 2 + tl;
    const int b = token >> 12;
    const int yx = token & 4095;
    const int y = yx >> 6, xx = yx & 63;

    if (threadIdx.x < 2) s_ss[threadIdx.x] = 0.f;

    // stage q into smem (all lanes need all 64 values in phase 1)
    const float* qrow = g_qkv + (size_t)token * QKVN + head * 64;
    s_q[warpId][lane]      = qrow[lane];
    s_q[warpId][lane + 32] = qrow[lane + 32];
    __syncwarp();

    const float width = g_wp[token * 8 + head];
    const float sharp = g_wp[token * 8 + 4 + head];

    // Phase 1: scores, lane = window
    float sc[2];
#pragma unroll
    for (int r = 0; r < 2; r++) {
        int w = lane + r * 32;
        bool act = (w < 49);
        int wc = act ? w : 0;
        int di = wc / 7 - 3, dj = wc % 7 - 3;
        int ny = y + di, nx = xx + dj;
        float dot = 0.f;
        if (act & ((unsigned)ny < 64u) & ((unsigned)nx < 64u)) {
            const float4* kr = (const float4*)(g_qkv +
                (size_t)((b << 12) + (ny << 6) + nx) * QKVN + 256 + head * 64);
            const float4* q4 = (const float4*)s_q[warpId];
            float d[4] = {0.f, 0.f, 0.f, 0.f};
#pragma unroll
            for (int i = 0; i < 16; i++) {
                float4 a = q4[i], kk = kr[i];
                d[i & 3] += a.x * kk.x + a.y * kk.y + a.z * kk.z + a.w * kk.w;
            }
            dot = (d[0] + d[1]) + (d[2] + d[3]);
        }
        if (act) {
            float rd = sqrtf((float)(di * di + dj * dj));
            float mask = fsig((width - rd) * sharp);
            sc[r] = dot * 0.125f - (1.f - mask) * 10000.f;
        } else {
            sc[r] = -1e30f;
        }
    }

    // Phase 2: warp softmax over 49 lane-held scores
    float mx = fmaxf(sc[0], sc[1]);
#pragma unroll
    for (int off = 16; off; off >>= 1) mx = fmaxf(mx, __shfl_xor_sync(0xffffffffu, mx, off));
    float p0 = __expf(sc[0] - mx);
    float p1 = __expf(sc[1] - mx);
    float ds = p0 + p1;
#pragma unroll
    for (int off = 16; off; off >>= 1) ds += __shfl_xor_sync(0xffffffffu, ds, off);
    float rdm = 1.f / ds;
    s_p[warpId][lane] = p0 * rdm;
    if (lane + 32 < 49) s_p[warpId][lane + 32] = p1 * rdm;
    __syncwarp();

    // Phase 3: lane = channel (d = lane, lane+32), coalesced v gathers
    float o0 = 0.f, o1 = 0.f;
#pragma unroll
    for (int ii = 0; ii < 7; ii++) {
        int ny = y + ii - 3;
        if ((unsigned)ny >= 64u) continue;
#pragma unroll
        for (int jj = 0; jj < 7; jj++) {
            int nx = xx + jj - 3;
            if ((unsigned)nx >= 64u) continue;
            float p = s_p[warpId][ii * 7 + jj];
            const float* vrow = g_qkv +
                (size_t)((b << 12) + (ny << 6) + nx) * QKVN + 512 + head * 64;
            o0 += p * vrow[lane];
            o1 += p * vrow[lane + 32];
        }
    }

    s_out[tl][head * 64 + lane]      = o0;
    s_out[tl][head * 64 + lane + 32] = o1;

    float pss = o0 * o0 + o1 * o1;
#pragma unroll
    for (int off = 16; off; off >>= 1) pss += __shfl_xor_sync(0xffffffffu, pss, off);
    __syncthreads();            // s_ss init + s_out visible
    if (lane == 0) atomicAdd(&s_ss[tl], pss);
    __syncthreads();

    for (int e = threadIdx.x; e < 512; e += 256) {
        int t2 = e >> 8, c = e & 255;
        float rinv = rsqrtf(s_ss[t2] * (1.f / 256.f) + 1e-6f);
        g_outn[(size_t)(blockIdx.x * 2 + t2) * CDIM + c] = s_out[t2][c] * rinv * w_onorm[c];
    }
}

// ---------------------------------------------------------------------------
extern "C" void kernel_launch(void* const* d_in, const int* in_sizes, int n_in,
                              void* d_out, int out_size)
{
    const float* x       = (const float*)d_in[0];
    const float* W_qkv   = (const float*)d_in[1];
    const float* w_qnorm = (const float*)d_in[2];
    const float* w_knorm = (const float*)d_in[3];
    const float* W_wp    = (const float*)d_in[4];
    const float* b_wp    = (const float*)d_in[5];
    const float* w_onorm = (const float*)d_in[6];
    const float* W_out   = (const float*)d_in[7];
    const float* W_gate  = (const float*)d_in[8];
    const float* b_gate  = (const float*)d_in[9];
    float* out = (float*)d_out;

    float *p_qkv, *p_wp, *p_outn, *p_merged;
    cudaGetSymbolAddress((void**)&p_qkv, g_qkv);
    cudaGetSymbolAddress((void**)&p_wp, g_wp);
    cudaGetSymbolAddress((void**)&p_outn, g_outn);
    cudaGetSymbolAddress((void**)&p_merged, g_merged);

    // 1. qkv = silu(x @ W_qkv)
    gemm_k256<0><<<dim3(NTOK / 128, QKVN / 64), 256>>>(x, CDIM, W_qkv, QKVN, nullptr,
                                                       p_qkv, QKVN, nullptr);
    // 2. width/sharpness projection
    wp_kernel<<<NTOK / 8, 256>>>(x, W_wp, b_wp, p_wp);
    // 3. rmsnorm + rope on q, k (in place)
    rmsrope_kernel<<<NTOK, 256>>>(w_qnorm, w_knorm);
    // 4. windowed attention + fused output rmsnorm
    attn_kernel<<<NTOK / 2, 256>>>(w_onorm);
    // 5. gate GEMM + merge epilogue: merged = gate*v + (1-gate)*outn
    gemm_k256<1><<<dim3(NTOK / 128, CDIM / 64), 256>>>(p_qkv + 512, QKVN, W_gate, CDIM,
                                                       b_gate, p_merged, CDIM, p_outn);
    // 6. final: silu(merged @ W_out)
    gemm_k256<0><<<dim3(NTOK / 128, CDIM / 64), 256>>>(p_merged, CDIM, W_out, CDIM, nullptr,
                                                       out, CDIM, nullptr);
}

// round 4
// speedup vs baseline: 1.9972x; 1.2085x over previous
#include <cuda_runtime.h>

// ---------------------------------------------------------------------------
// LocalAttentionND: x(2,64,64,256) -> qkv GEMM -> rmsnorm+rope -> 7x7 local
// soft-masked attention -> rmsnorm -> gate merge -> out GEMM.
// Round 3: attention phase-1 uses 4x8-lane groups -> fully coalesced k loads
// (104 L1 wavefronts vs 512); GEMM software-pipelines its global loads.
// ---------------------------------------------------------------------------

static constexpr int NTOK = 8192;      // 2*64*64
static constexpr int CDIM = 256;
static constexpr int QKVN = 768;

__device__ float g_qkv[NTOK * QKVN];     // silu(x@W_qkv); q/k rewritten in-place
__device__ float g_wp[NTOK * 8];         // width[4], sharp[4] per token
__device__ float g_outn[NTOK * CDIM];    // rmsnorm(attention out)
__device__ float g_merged[NTOK * CDIM];  // gate*v + (1-gate)*outn

__device__ __forceinline__ float fsig(float x)  { return 1.f / (1.f + __expf(-x)); }
__device__ __forceinline__ float fsilu(float x) { return x   / (1.f + __expf(-x)); }

// ---------------------------------------------------------------------------
// GEMM: Cout = epi(A[M,256] @ W[256,N] (+bias)). Tile 128x64x16, 256 thr,
// 8x4 microtile, pipelined global->smem staging.
// EPI=0: silu. EPI=1: gate-merge (A is v, outn blended in).
// ---------------------------------------------------------------------------
template <int EPI>
__global__ void __launch_bounds__(256) gemm_k256(
    const float* __restrict__ A, int lda,
    const float* __restrict__ W, int ldw,
    const float* __restrict__ bias,
    float* __restrict__ Cout, int ldc,
    const float* __restrict__ outn)
{
    __shared__ __align__(16) float As[16][132];  // [k][m]
    __shared__ __align__(16) float Bs[16][64];   // [k][n]

    const int tid = threadIdx.x;
    const int tx = tid & 15;
    const int ty = tid >> 4;
    const int row0 = blockIdx.x * 128;
    const int col0 = blockIdx.y * 64;

    const int arow = tid >> 1;           // 0..127
    const int acol = (tid & 1) * 8;      // 0 or 8
    const int brow = tid >> 4;           // 0..15
    const int bcol = (tid & 15) * 4;     // 0..60

    const float* Ap = A + (size_t)(row0 + arow) * lda + acol;
    const float* Wp = W + (size_t)brow * ldw + col0 + bcol;

    float acc[8][4] = {};

    // prologue: load first slab
    float4 na0 = *(const float4*)(Ap);
    float4 na1 = *(const float4*)(Ap + 4);
    float4 nb  = *(const float4*)(Wp);

    for (int k0 = 0; k0 < 256; k0 += 16) {
        As[acol + 0][arow] = na0.x; As[acol + 1][arow] = na0.y;
        As[acol + 2][arow] = na0.z; As[acol + 3][arow] = na0.w;
        As[acol + 4][arow] = na1.x; As[acol + 5][arow] = na1.y;
        As[acol + 6][arow] = na1.z; As[acol + 7][arow] = na1.w;
        *(float4*)&Bs[brow][bcol] = nb;
        __syncthreads();

        if (k0 + 16 < 256) {   // prefetch next slab; overlaps MMA below
            na0 = *(const float4*)(Ap + k0 + 16);
            na1 = *(const float4*)(Ap + k0 + 20);
            nb  = *(const float4*)(Wp + (size_t)(k0 + 16) * ldw);
        }

#pragma unroll
        for (int kk = 0; kk < 16; kk++) {
            float4 b  = *(const float4*)&Bs[kk][tx * 4];
            float4 x0 = *(const float4*)&As[kk][ty * 8];
            float4 x1 = *(const float4*)&As[kk][ty * 8 + 4];
            float av[8] = {x0.x, x0.y, x0.z, x0.w, x1.x, x1.y, x1.z, x1.w};
#pragma unroll
            for (int i = 0; i < 8; i++) {
                acc[i][0] += av[i] * b.x;
                acc[i][1] += av[i] * b.y;
                acc[i][2] += av[i] * b.z;
                acc[i][3] += av[i] * b.w;
            }
        }
        __syncthreads();
    }

#pragma unroll
    for (int i = 0; i < 8; i++) {
        int row = row0 + ty * 8 + i;
        int col = col0 + tx * 4;
        float4 r;
        if (EPI == 0) {
            r.x = fsilu(acc[i][0]);
            r.y = fsilu(acc[i][1]);
            r.z = fsilu(acc[i][2]);
            r.w = fsilu(acc[i][3]);
        } else {
            float4 v4 = *(const float4*)(A + (size_t)row * lda + col);
            float4 o4 = *(const float4*)(outn + (size_t)row * CDIM + col);
            float4 b4 = *(const float4*)(bias + col);
            float g;
            g = fsig(fsilu(acc[i][0] + b4.x)); r.x = g * v4.x + (1.f - g) * o4.x;
            g = fsig(fsilu(acc[i][1] + b4.y)); r.y = g * v4.y + (1.f - g) * o4.y;
            g = fsig(fsilu(acc[i][2] + b4.z)); r.z = g * v4.z + (1.f - g) * o4.z;
            g = fsig(fsilu(acc[i][3] + b4.w)); r.w = g * v4.w + (1.f - g) * o4.w;
        }
        *(float4*)(Cout + (size_t)row * ldc + col) = r;
    }
}

// ---------------------------------------------------------------------------
// wp = silu(x @ W_wp + b_wp); width = sig(.)*maxd+0.5, sharp = sig(.)*9.5+0.5
// ---------------------------------------------------------------------------
__global__ void __launch_bounds__(256) wp_kernel(
    const float* __restrict__ x, const float* __restrict__ W_wp,
    const float* __restrict__ b_wp, float* __restrict__ wp_out)
{
    int warp = (blockIdx.x * blockDim.x + threadIdx.x) >> 5;
    int lane = threadIdx.x & 31;
    if (warp >= NTOK) return;
    const float* xr = x + (size_t)warp * CDIM;
    float acc[8] = {};
    for (int k = lane; k < CDIM; k += 32) {
        float xv = xr[k];
        const float* wr = W_wp + k * 8;
#pragma unroll
        for (int o = 0; o < 8; o++) acc[o] += xv * wr[o];
    }
#pragma unroll
    for (int o = 0; o < 8; o++)
#pragma unroll
        for (int off = 16; off; off >>= 1)
            acc[o] += __shfl_xor_sync(0xffffffffu, acc[o], off);
    if (lane < 8) {
        const float maxd = 4.242640687119285f;  // sqrt(18)
        float t = acc[lane] + b_wp[lane];
        float s = fsilu(t);
        float sg = fsig(s);
        wp_out[warp * 8 + lane] = (lane < 4) ? (sg * maxd + 0.5f) : (sg * 9.5f + 0.5f);
    }
}

// ---------------------------------------------------------------------------
// In-place rmsnorm (per head, D=64) + RoPE (position = head index) on q, k.
// ---------------------------------------------------------------------------
__global__ void __launch_bounds__(256) rmsrope_kernel(
    const float* __restrict__ w_qnorm, const float* __restrict__ w_knorm)
{
    int token = blockIdx.x;
    int warpId = threadIdx.x >> 5, lane = threadIdx.x & 31;
    int which = warpId >> 2;    // 0=q, 1=k
    int head  = warpId & 3;
    const float* wn = which ? w_knorm : w_qnorm;
    float* base = g_qkv + (size_t)token * QKVN + which * CDIM + head * 64;

    float x1 = base[lane], x2 = base[lane + 32];
    float ss = x1 * x1 + x2 * x2;
#pragma unroll
    for (int off = 16; off; off >>= 1) ss += __shfl_xor_sync(0xffffffffu, ss, off);
    float inv = rsqrtf(ss * (1.f / 64.f) + 1e-6f);
    x1 = x1 * inv * wn[lane];
    x2 = x2 * inv * wn[lane + 32];

    float freq = exp2f(-(float)lane * (13.287712379549449f / 32.f));  // log2(10000)/32
    float ang = (float)head * freq;
    float c = cosf(ang), s = sinf(ang);
    base[lane]      = x1 * c - x2 * s;
    base[lane + 32] = x1 * s + x2 * c;
}

// ---------------------------------------------------------------------------
// Attention: 1 warp per (token, head), 2 tokens per 256-thread block.
// Phase 1: 4 groups of 8 lanes; group = window, lane = 8 channels. Every
//          LDG.128 covers 4 rows x 128B contiguous = 4 full lines (coalesced).
//          Dot reduced with 3 intra-group butterflies. 13 rounds cover 49 wins.
// Phase 2: warp softmax (scores via smem).
// Phase 3: lane = channel, coalesced v gathers. Fused per-token rmsnorm.
// OOB windows: dot=0 / v=0 (ref zero-padding) but mask penalty still applies.
// ---------------------------------------------------------------------------
__global__ void __launch_bounds__(256) attn_kernel(const float* __restrict__ w_onorm)
{
    __shared__ __align__(16) float s_q[8][64];
    __shared__ float s_p[8][52];
    __shared__ float s_out[2][256];
    __shared__ float s_ss[2];

    const int warpId = threadIdx.x >> 5, lane = threadIdx.x & 31;
    const int tl = warpId >> 2;      // token-local 0/1
    const int head = warpId & 3;
    const int token = blockIdx.x * 2 + tl;
    const int b = token >> 12;
    const int yx = token & 4095;
    const int y = yx >> 6, xx = yx & 63;

    if (threadIdx.x < 2) s_ss[threadIdx.x] = 0.f;

    // stage q into smem, then pull this lane's 8 channels into registers
    const float* qrow = g_qkv + (size_t)token * QKVN + head * 64;
    s_q[warpId][lane]      = qrow[lane];
    s_q[warpId][lane + 32] = qrow[lane + 32];
    __syncwarp();

    const int sub = lane & 7;        // lane within group
    const int grp = lane >> 3;       // group = window within round
    float4 q4a = ((const float4*)s_q[warpId])[sub];
    float4 q4b = ((const float4*)s_q[warpId])[sub + 8];

    const float width = g_wp[token * 8 + head];
    const float sharp = g_wp[token * 8 + 4 + head];
    const float* kbase = g_qkv + 256 + (size_t)head * 64;

    // Phase 1: scores, 4 windows per round
#pragma unroll
    for (int r = 0; r < 13; r++) {
        int w = r * 4 + grp;
        bool act = (w < 49);
        int wc = act ? w : 48;
        int di = wc / 7 - 3, dj = wc % 7 - 3;
        int ny = y + di, nx = xx + dj;
        float part = 0.f;
        if (act & ((unsigned)ny < 64u) & ((unsigned)nx < 64u)) {
            const float4* kr = (const float4*)(kbase +
                (size_t)((b << 12) + (ny << 6) + nx) * QKVN);
            float4 ka = kr[sub];
            float4 kb = kr[sub + 8];
            part = q4a.x * ka.x + q4a.y * ka.y + q4a.z * ka.z + q4a.w * ka.w
                 + q4b.x * kb.x + q4b.y * kb.y + q4b.z * kb.z + q4b.w * kb.w;
        }
        part += __shfl_xor_sync(0xffffffffu, part, 1);
        part += __shfl_xor_sync(0xffffffffu, part, 2);
        part += __shfl_xor_sync(0xffffffffu, part, 4);
        if (act && sub == 0) {
            float rd = sqrtf((float)(di * di + dj * dj));
            float mask = fsig((width - rd) * sharp);
            s_p[warpId][w] = part * 0.125f - (1.f - mask) * 10000.f;
        }
    }
    __syncwarp();

    // Phase 2: warp softmax over 49 scores in smem
    float sc0 = s_p[warpId][lane];
    float sc1 = (lane + 32 < 49) ? s_p[warpId][lane + 32] : -1e30f;
    float mx = fmaxf(sc0, sc1);
#pragma unroll
    for (int off = 16; off; off >>= 1) mx = fmaxf(mx, __shfl_xor_sync(0xffffffffu, mx, off));
    float p0 = __expf(sc0 - mx);
    float p1 = __expf(sc1 - mx);
    float ds = p0 + p1;
#pragma unroll
    for (int off = 16; off; off >>= 1) ds += __shfl_xor_sync(0xffffffffu, ds, off);
    float rdm = 1.f / ds;
    s_p[warpId][lane] = p0 * rdm;
    if (lane + 32 < 49) s_p[warpId][lane + 32] = p1 * rdm;
    __syncwarp();

    // Phase 3: lane = channel (d = lane, lane+32), coalesced v gathers
    float o0 = 0.f, o1 = 0.f;
#pragma unroll
    for (int ii = 0; ii < 7; ii++) {
        int ny = y + ii - 3;
        if ((unsigned)ny >= 64u) continue;
#pragma unroll
        for (int jj = 0; jj < 7; jj++) {
            int nx = xx + jj - 3;
            if ((unsigned)nx >= 64u) continue;
            float p = s_p[warpId][ii * 7 + jj];
            const float* vrow = g_qkv +
                (size_t)((b << 12) + (ny << 6) + nx) * QKVN + 512 + head * 64;
            o0 += p * vrow[lane];
            o1 += p * vrow[lane + 32];
        }
    }

    s_out[tl][head * 64 + lane]      = o0;
    s_out[tl][head * 64 + lane + 32] = o1;

    float pss = o0 * o0 + o1 * o1;
#pragma unroll
    for (int off = 16; off; off >>= 1) pss += __shfl_xor_sync(0xffffffffu, pss, off);
    __syncthreads();            // s_ss init + s_out visible
    if (lane == 0) atomicAdd(&s_ss[tl], pss);
    __syncthreads();

    for (int e = threadIdx.x; e < 512; e += 256) {
        int t2 = e >> 8, c = e & 255;
        float rinv = rsqrtf(s_ss[t2] * (1.f / 256.f) + 1e-6f);
        g_outn[(size_t)(blockIdx.x * 2 + t2) * CDIM + c] = s_out[t2][c] * rinv * w_onorm[c];
    }
}

// ---------------------------------------------------------------------------
extern "C" void kernel_launch(void* const* d_in, const int* in_sizes, int n_in,
                              void* d_out, int out_size)
{
    const float* x       = (const float*)d_in[0];
    const float* W_qkv   = (const float*)d_in[1];
    const float* w_qnorm = (const float*)d_in[2];
    const float* w_knorm = (const float*)d_in[3];
    const float* W_wp    = (const float*)d_in[4];
    const float* b_wp    = (const float*)d_in[5];
    const float* w_onorm = (const float*)d_in[6];
    const float* W_out   = (const float*)d_in[7];
    const float* W_gate  = (const float*)d_in[8];
    const float* b_gate  = (const float*)d_in[9];
    float* out = (float*)d_out;

    float *p_qkv, *p_wp, *p_outn, *p_merged;
    cudaGetSymbolAddress((void**)&p_qkv, g_qkv);
    cudaGetSymbolAddress((void**)&p_wp, g_wp);
    cudaGetSymbolAddress((void**)&p_outn, g_outn);
    cudaGetSymbolAddress((void**)&p_merged, g_merged);

    // 1. qkv = silu(x @ W_qkv)
    gemm_k256<0><<<dim3(NTOK / 128, QKVN / 64), 256>>>(x, CDIM, W_qkv, QKVN, nullptr,
                                                       p_qkv, QKVN, nullptr);
    // 2. width/sharpness projection
    wp_kernel<<<NTOK / 8, 256>>>(x, W_wp, b_wp, p_wp);
    // 3. rmsnorm + rope on q, k (in place)
    rmsrope_kernel<<<NTOK, 256>>>(w_qnorm, w_knorm);
    // 4. windowed attention + fused output rmsnorm
    attn_kernel<<<NTOK / 2, 256>>>(w_onorm);
    // 5. gate GEMM + merge epilogue: merged = gate*v + (1-gate)*outn
    gemm_k256<1><<<dim3(NTOK / 128, CDIM / 64), 256>>>(p_qkv + 512, QKVN, W_gate, CDIM,
                                                       b_gate, p_merged, CDIM, p_outn);
    // 6. final: silu(merged @ W_out)
    gemm_k256<0><<<dim3(NTOK / 128, CDIM / 64), 256>>>(p_merged, CDIM, W_out, CDIM, nullptr,
                                                       out, CDIM, nullptr);
}